// round 16
// baseline (speedup 1.0000x reference)
#include <cuda_runtime.h>
#include <cuda_bf16.h>
#include <cuda_fp16.h>
#include <math.h>
#include <stdint.h>

#define NN 48758
#define EE 750000
#define D 128
#define RELS 5
#define PADK 136
#define WBYTES 69632
#define HBYTES 34816
#define NB 48

// ---------------- static device scratch ----------------
__device__ __align__(256) float g_buf0[NN * D];   // h (proj out); later cout1 out
__device__ __align__(256) float g_zg0[NN * D];    // layer0 gcn part
__device__ __align__(256) float g_zm0[NN * D];    // layer0 softmax part
__device__ __align__(256) float g_zg1[NN * D];    // layer1 gcn part
__device__ __align__(256) float g_zm1[NN * D];    // layer1 softmax part
__device__ __align__(256) __half g_x16[NN * D];
__device__ __align__(256) __half g_yh[(size_t)RELS * NN * D];
__device__ float g_bnsum[D];
__device__ float g_bnssum[D];
__device__ int   g_srccnt[NN];
__device__ int   g_dstcnt[NN];
__device__ float g_dis[NN];
__device__ int   g_rowoff[NN + 1];
__device__ int   g_cursor[NN];
__device__ int   g_scanloc[NN];
__device__ int   g_bsum[NB];
__device__ int   g_boff[NB];
__device__ int2  g_edge[EE];
__device__ __align__(256) unsigned char g_w[(size_t)15 * WBYTES];
__device__ float g_ybias[2 * RELS * D];
__device__ float g_xbias1[D];

// ---------------- helpers ----------------
__device__ __forceinline__ uint32_t smem_u32(const void* p) {
    uint32_t a;
    asm("{ .reg .u64 t; cvta.to.shared.u64 t, %1; cvt.u32.u64 %0, t; }" : "=r"(a) : "l"(p));
    return a;
}
__device__ __forceinline__ uint32_t pack_bf2(__nv_bfloat16 lo, __nv_bfloat16 hi) {
    return ((uint32_t)__bfloat16_as_ushort(hi) << 16) | (uint32_t)__bfloat16_as_ushort(lo);
}
__device__ __forceinline__ void split_pair(float x0, float x1, uint32_t& hi2, uint32_t& lo2) {
    __nv_bfloat16 h0 = __float2bfloat16(x0), h1 = __float2bfloat16(x1);
    __nv_bfloat16 l0 = __float2bfloat16(x0 - __bfloat162float(h0));
    __nv_bfloat16 l1 = __float2bfloat16(x1 - __bfloat162float(h1));
    hi2 = pack_bf2(h0, h1);
    lo2 = pack_bf2(l0, l1);
}
__device__ __forceinline__ void ldmx4(uint32_t* r, uint32_t addr) {
    asm volatile("ldmatrix.sync.aligned.m8n8.x4.shared.b16 {%0,%1,%2,%3}, [%4];"
                 : "=r"(r[0]), "=r"(r[1]), "=r"(r[2]), "=r"(r[3]) : "r"(addr));
}
__device__ __forceinline__ void ldmx4t(uint32_t* r, uint32_t addr) {
    asm volatile("ldmatrix.sync.aligned.m8n8.x4.trans.shared.b16 {%0,%1,%2,%3}, [%4];"
                 : "=r"(r[0]), "=r"(r[1]), "=r"(r[2]), "=r"(r[3]) : "r"(addr));
}
__device__ __forceinline__ void mma16816(float* c, const uint32_t* a, const uint32_t* b) {
    asm volatile(
        "mma.sync.aligned.m16n8k16.row.col.f32.bf16.bf16.f32 "
        "{%0,%1,%2,%3}, {%4,%5,%6,%7}, {%8,%9}, {%0,%1,%2,%3};"
        : "+f"(c[0]), "+f"(c[1]), "+f"(c[2]), "+f"(c[3])
        : "r"(a[0]), "r"(a[1]), "r"(a[2]), "r"(a[3]), "r"(b[0]), "r"(b[1]));
}
__device__ __forceinline__ void cpasync16(uint32_t sdst, const void* gsrc) {
    asm volatile("cp.async.cg.shared.global [%0], [%1], 16;" :: "r"(sdst), "l"(gsrc) : "memory");
}
__device__ __forceinline__ void cp_commit() {
    asm volatile("cp.async.commit_group;" ::: "memory");
}

// ---------------- prep kernels ----------------
__device__ void split_direct(const float* __restrict__ W, unsigned char* dst) {
    for (int idx = threadIdx.x; idx < 128 * 64; idx += blockDim.x) {
        int k = idx >> 6, n = (idx & 63) * 2;
        uint32_t hi2, lo2;
        split_pair(W[k * 128 + n], W[k * 128 + n + 1], hi2, lo2);
        *(uint32_t*)(dst + (size_t)(k * PADK + n) * 2) = hi2;
        *(uint32_t*)(dst + HBYTES + (size_t)(k * PADK + n) * 2) = lo2;
    }
}

__device__ __forceinline__ float dot128(const float* __restrict__ left_row,
                                        const float* __restrict__ ws, int n) {
    float acc = 0.f;
#pragma unroll 8
    for (int j = 0; j < 128; j++) acc = fmaf(left_row[j], ws[j * 128 + n], acc);
    return acc;
}

__global__ void prep_fast(const float* __restrict__ proj,
                          const float* __restrict__ win0,
                          const float* __restrict__ cout1) {
    int b = blockIdx.x;
    if (b == 0) split_direct(proj,  g_w + 0 * (size_t)WBYTES);
    else if (b == 1) split_direct(win0, g_w + 1 * (size_t)WBYTES);
    else split_direct(cout1, g_w + 14 * (size_t)WBYTES);
}

__global__ void prep_comp0(const float* __restrict__ win0, const float* __restrict__ wrel0,
                           const float* __restrict__ win0b) {
    extern __shared__ float ws1[];
    int r = blockIdx.x, tid = threadIdx.x;
    const float* wrl = wrel0 + (size_t)r * 16384;
    unsigned char* dst = g_w + (size_t)(2 + r) * WBYTES;
    for (int i = tid; i < 4096; i += blockDim.x)
        ((float4*)ws1)[i] = ((const float4*)wrl)[i];
    __syncthreads();
    int n = tid & 127;
    int kbase = (tid >> 7) * 32;
    for (int ko = 0; ko < 32; ko++) {
        int k = kbase + ko;
        float acc = dot128(win0 + (size_t)k * 128, ws1, n);
        *(unsigned short*)(dst + (size_t)(k * PADK + n) * 2) =
            __bfloat16_as_ushort(__float2bfloat16(acc));
    }
    if (tid < 128) {
        float acc = 0.f;
#pragma unroll 8
        for (int k = 0; k < 128; k++) acc = fmaf(win0b[k], ws1[k * 128 + tid], acc);
        g_ybias[r * D + tid] = acc;
    }
}

__global__ void prep_layer1(const float* __restrict__ cout0, const float* __restrict__ win1,
                            const float* __restrict__ wrel1,
                            const float* __restrict__ win1b, const float* __restrict__ cout0b) {
    extern __shared__ float ws[];
    float* ws1 = ws;
    float* ws2 = ws + 16384;
    int b = blockIdx.x, tid = threadIdx.x;
    int n = tid & 127;
    int kbase = (tid >> 7) * 32;

    if (b == 0) {
        unsigned char* dst = g_w + (size_t)8 * WBYTES;
        for (int i = tid; i < 4096; i += blockDim.x)
            ((float4*)ws1)[i] = ((const float4*)win1)[i];
        __syncthreads();
        for (int ko = 0; ko < 32; ko++) {
            int k = kbase + ko;
            float acc = dot128(cout0 + (size_t)k * 128, ws1, n);
            __nv_bfloat16 h = __float2bfloat16(acc);
            __nv_bfloat16 l = __float2bfloat16(acc - __bfloat162float(h));
            *(unsigned short*)(dst + (size_t)(k * PADK + n) * 2) = __bfloat16_as_ushort(h);
            *(unsigned short*)(dst + HBYTES + (size_t)(k * PADK + n) * 2) = __bfloat16_as_ushort(l);
        }
        if (tid < 128) {
            float acc = win1b[tid];
#pragma unroll 8
            for (int k = 0; k < 128; k++) acc = fmaf(cout0b[k], ws1[k * 128 + tid], acc);
            g_xbias1[tid] = acc;
        }
        return;
    }

    int r = b - 1;
    const float* wrl = wrel1 + (size_t)r * 16384;
    unsigned char* dst = g_w + (size_t)(9 + r) * WBYTES;
    for (int i = tid; i < 4096; i += blockDim.x)
        ((float4*)ws1)[i] = ((const float4*)wrl)[i];
    __syncthreads();
    for (int ko = 0; ko < 32; ko++) {
        int k = kbase + ko;
        ws2[k * 128 + n] = dot128(win1 + (size_t)k * 128, ws1, n);
    }
    __syncthreads();
    for (int ko = 0; ko < 32; ko++) {
        int k = kbase + ko;
        float acc = dot128(cout0 + (size_t)k * 128, ws2, n);
        *(unsigned short*)(dst + (size_t)(k * PADK + n) * 2) =
            __bfloat16_as_ushort(__float2bfloat16(acc));
    }
    if (tid < 128) {
        float acc = 0.f;
#pragma unroll 8
        for (int k = 0; k < 128; k++) {
            acc = fmaf(cout0b[k], ws2[k * 128 + tid], acc);
            acc = fmaf(win1b[k], ws1[k * 128 + tid], acc);
        }
        g_ybias[(RELS + r) * D + tid] = acc;
    }
}

// ---------------- mma compute core ----------------
template<int NC>
__device__ __forceinline__ void mma_compute(
    const char* Abase, const char* Bbase, float acc[2][8][4], int wm, int wn, int lane)
{
#pragma unroll
    for (int mt = 0; mt < 2; mt++)
#pragma unroll
        for (int nt = 0; nt < 8; nt++)
#pragma unroll
            for (int i = 0; i < 4; i++) acc[mt][nt][i] = 0.f;

    const int arow = (lane & 15);
    const int acolb = (lane >> 4) * 8;

#pragma unroll
    for (int cb = 0; cb < NC; cb++) {
        const char* As = Abase + (cb == 2 ? HBYTES : 0);
        const char* Bs = Bbase + (cb == 1 ? HBYTES : 0);
#pragma unroll
        for (int k16 = 0; k16 < 8; k16++) {
            int k0 = k16 * 16;
            uint32_t afrag[2][4];
#pragma unroll
            for (int mt = 0; mt < 2; mt++) {
                int rr = wm * 32 + mt * 16 + arow;
                ldmx4(afrag[mt], smem_u32(As + (size_t)(rr * PADK + k0 + acolb) * 2));
            }
            uint32_t bfrag[8][2];
#pragma unroll
            for (int nt2 = 0; nt2 < 4; nt2++) {
                int rr = k0 + arow;
                int c = wn * 64 + nt2 * 16 + acolb;
                uint32_t t[4];
                ldmx4t(t, smem_u32(Bs + (size_t)(rr * PADK + c) * 2));
                bfrag[nt2 * 2][0] = t[0]; bfrag[nt2 * 2][1] = t[1];
                bfrag[nt2 * 2 + 1][0] = t[2]; bfrag[nt2 * 2 + 1][1] = t[3];
            }
#pragma unroll
            for (int mt = 0; mt < 2; mt++)
#pragma unroll
                for (int nt = 0; nt < 8; nt++)
                    mma16816(acc[mt][nt], afrag[mt], bfrag[nt]);
        }
    }
}

// stage_A with optional second operand (combined z = A + A2) and optional BN
__device__ __forceinline__ void stage_A(char* smem, const float* __restrict__ A,
                                        const float* __restrict__ A2,
                                        int rowBase, int M, int aoff,
                                        const float* bnsc, const float* bnsh) {
    for (int idx = threadIdx.x; idx < 128 * 64; idx += 256) {
        int row = idx >> 6, k = (idx & 63) * 2;
        int gr = rowBase + row; if (gr >= M) gr = M - 1;
        float2 a = *(const float2*)(A + (size_t)gr * D + k);
        if (A2) {
            float2 b = *(const float2*)(A2 + (size_t)gr * D + k);
            a.x += b.x; a.y += b.y;
        }
        if (bnsc) {
            a.x = fmaxf(fmaf(a.x, bnsc[k], bnsh[k]), 0.f);
            a.y = fmaxf(fmaf(a.y, bnsc[k + 1], bnsh[k + 1]), 0.f);
        }
        uint32_t hi2, lo2;
        split_pair(a.x, a.y, hi2, lo2);
        *(uint32_t*)(smem + aoff + (size_t)(row * PADK + k) * 2) = hi2;
        *(uint32_t*)(smem + aoff + HBYTES + (size_t)(row * PADK + k) * 2) = lo2;
    }
}

__device__ __forceinline__ void stage_A_hi(char* smem, const float* __restrict__ A,
                                           const float* __restrict__ A2,
                                           int rowBase, int M, int aoff,
                                           const float* bnsc, const float* bnsh) {
    for (int idx = threadIdx.x; idx < 128 * 64; idx += 256) {
        int row = idx >> 6, k = (idx & 63) * 2;
        int gr = rowBase + row; if (gr >= M) gr = M - 1;
        float2 a = *(const float2*)(A + (size_t)gr * D + k);
        if (A2) {
            float2 b = *(const float2*)(A2 + (size_t)gr * D + k);
            a.x += b.x; a.y += b.y;
        }
        if (bnsc) {
            a.x = fmaxf(fmaf(a.x, bnsc[k], bnsh[k]), 0.f);
            a.y = fmaxf(fmaf(a.y, bnsc[k + 1], bnsh[k + 1]), 0.f);
        }
        uint32_t hi2 = pack_bf2(__float2bfloat16(a.x), __float2bfloat16(a.y));
        *(uint32_t*)(smem + aoff + (size_t)(row * PADK + k) * 2) = hi2;
    }
}

__device__ __forceinline__ void bn_coefs_smem(float* bnsc, float* bnsh,
                                              const float* bn_g, const float* bn_b) {
    int tid = threadIdx.x;
    if (tid < 128) {
        float mu = g_bnsum[tid] * (1.f / NN);
        float var = g_bnssum[tid] * (1.f / NN) - mu * mu;
        float sc = bn_g[tid] * rsqrtf(var + 1e-5f);
        bnsc[tid] = sc;
        bnsh[tid] = bn_b[tid] - mu * sc;
    }
}

// ---------------- gemm_mma (cout1): C = (A+A2) @ W + bias ----------------
#define SM_AHI  0
#define SM_BHI  69632
#define SM_BIAS 139264
#define SM_TOTAL 139776

__global__ __launch_bounds__(256, 1) void gemm_mma(
    const float* __restrict__ A, const float* __restrict__ A2,
    const unsigned char* __restrict__ Wp,
    const float* __restrict__ bias, float* __restrict__ C, int M)
{
    extern __shared__ char smem[];
    int tid = threadIdx.x, wid = tid >> 5, lane = tid & 31;
    int wm = wid & 3, wn = wid >> 2;
    int rowBase = blockIdx.x * 128;

    for (int i = tid; i < WBYTES / 16; i += 256)
        ((float4*)(smem + SM_BHI))[i] = ((const float4*)Wp)[i];
    if (tid < 128) ((float*)(smem + SM_BIAS))[tid] = bias[tid];
    stage_A(smem, A, A2, rowBase, M, SM_AHI, nullptr, nullptr);
    __syncthreads();

    float acc[2][8][4];
    mma_compute<3>(smem + SM_AHI, smem + SM_BHI, acc, wm, wn, lane);

    const float* bs = (const float*)(smem + SM_BIAS);
    int r0 = rowBase + wm * 32 + (lane >> 2);
    int cb0 = wn * 64 + (lane & 3) * 2;
#pragma unroll
    for (int mt = 0; mt < 2; mt++)
#pragma unroll
        for (int half = 0; half < 2; half++) {
            int row = r0 + mt * 16 + half * 8;
            if (row < M) {
                float* crow = C + (size_t)row * D;
#pragma unroll
                for (int nt = 0; nt < 8; nt++) {
                    int col = cb0 + nt * 8;
                    float2 v = { acc[mt][nt][half * 2] + bs[col],
                                 acc[mt][nt][half * 2 + 1] + bs[col + 1] };
                    *(float2*)(crow + col) = v;
                }
            }
        }
}

// ---------------- proj GEMM with fused BN-stats ----------------
#define SMP_STAT  139776
#define SMP_TOTAL 140800

__global__ __launch_bounds__(256, 1) void gemm_proj(
    const float* __restrict__ A, const unsigned char* __restrict__ Wp,
    const float* __restrict__ bias, float* __restrict__ C, int M)
{
    extern __shared__ char smem[];
    int tid = threadIdx.x, wid = tid >> 5, lane = tid & 31;
    int wm = wid & 3, wn = wid >> 2;
    int rowBase = blockIdx.x * 128;

    float* ssum = (float*)(smem + SMP_STAT);
    float* ssq  = ssum + 128;
    if (tid < 128) { ssum[tid] = 0.f; ssq[tid] = 0.f; }

    for (int i = tid; i < WBYTES / 16; i += 256)
        ((float4*)(smem + SM_BHI))[i] = ((const float4*)Wp)[i];
    if (tid < 128) ((float*)(smem + SM_BIAS))[tid] = bias[tid];
    stage_A(smem, A, nullptr, rowBase, M, SM_AHI, nullptr, nullptr);
    __syncthreads();

    float acc[2][8][4];
    mma_compute<3>(smem + SM_AHI, smem + SM_BHI, acc, wm, wn, lane);

    const float* bs = (const float*)(smem + SM_BIAS);
    int r0 = rowBase + wm * 32 + (lane >> 2);
    int cb0 = wn * 64 + (lane & 3) * 2;

    float cs[16], cq[16];
#pragma unroll
    for (int i = 0; i < 16; i++) { cs[i] = 0.f; cq[i] = 0.f; }

#pragma unroll
    for (int mt = 0; mt < 2; mt++)
#pragma unroll
        for (int half = 0; half < 2; half++) {
            int row = r0 + mt * 16 + half * 8;
            if (row < M) {
                float* crow = C + (size_t)row * D;
#pragma unroll
                for (int nt = 0; nt < 8; nt++) {
                    int col = cb0 + nt * 8;
                    float v0 = acc[mt][nt][half * 2] + bs[col];
                    float v1 = acc[mt][nt][half * 2 + 1] + bs[col + 1];
                    float2 v = { v0, v1 };
                    *(float2*)(crow + col) = v;
                    cs[nt * 2] += v0;      cq[nt * 2] = fmaf(v0, v0, cq[nt * 2]);
                    cs[nt * 2 + 1] += v1;  cq[nt * 2 + 1] = fmaf(v1, v1, cq[nt * 2 + 1]);
                }
            }
        }

#pragma unroll
    for (int nt = 0; nt < 8; nt++) {
        int col = cb0 + nt * 8;
        atomicAdd(&ssum[col], cs[nt * 2]);      atomicAdd(&ssq[col], cq[nt * 2]);
        atomicAdd(&ssum[col + 1], cs[nt * 2 + 1]); atomicAdd(&ssq[col + 1], cq[nt * 2 + 1]);
    }
    __syncthreads();
    if (tid < 128) {
        atomicAdd(&g_bnsum[tid], ssum[tid]);
        atomicAdd(&g_bnssum[tid], ssq[tid]);
    }
}

// ---------------- gemm_x: xlin fp16 out, 3-combo ----------------
#define SMX_A    0
#define SMX_B    69632
#define SMX_BIAS 139264
#define SMX_BN   139776
#define SMX_TOTAL 140800

__global__ __launch_bounds__(256, 1) void gemm_x(
    const float* __restrict__ A, const float* __restrict__ A2,
    const unsigned char* __restrict__ Wp,
    const float* __restrict__ bias, const float* __restrict__ bn_g,
    const float* __restrict__ bn_b, __half* __restrict__ x16, int M, int bnflag)
{
    extern __shared__ char smem[];
    int tid = threadIdx.x, wid = tid >> 5, lane = tid & 31;
    int wm = wid & 3, wn = wid >> 2;
    int rowBase = blockIdx.x * 128;

    float* bnsc = (float*)(smem + SMX_BN);
    float* bnsh = bnsc + 128;
    if (bnflag) bn_coefs_smem(bnsc, bnsh, bn_g, bn_b);

    for (int i = tid; i < WBYTES / 16; i += 256)
        ((float4*)(smem + SMX_B))[i] = ((const float4*)Wp)[i];
    if (tid < 128) ((float*)(smem + SMX_BIAS))[tid] = bias[tid];
    __syncthreads();
    stage_A(smem, A, A2, rowBase, M, SMX_A, bnflag ? bnsc : nullptr, bnflag ? bnsh : nullptr);
    __syncthreads();

    float acc[2][8][4];
    mma_compute<3>(smem + SMX_A, smem + SMX_B, acc, wm, wn, lane);

    const float* bs = (const float*)(smem + SMX_BIAS);
    int r0 = rowBase + wm * 32 + (lane >> 2);
    int cb0 = wn * 64 + (lane & 3) * 2;
#pragma unroll
    for (int mt = 0; mt < 2; mt++)
#pragma unroll
        for (int half = 0; half < 2; half++) {
            int row = r0 + mt * 16 + half * 8;
            if (row < M) {
                __half* crow = x16 + (size_t)row * D;
#pragma unroll
                for (int nt = 0; nt < 8; nt++) {
                    int col = cb0 + nt * 8;
                    __half2 v = __floats2half2_rn(acc[mt][nt][half * 2] + bs[col],
                                                  acc[mt][nt][half * 2 + 1] + bs[col + 1]);
                    *(__half2*)(crow + col) = v;
                }
            }
        }
}

// ---------------- gemm_y5: 5 composites, single-combo, 2 CTAs/SM ----------------
#define Y5_A    0
#define Y5_B0   34816
#define Y5_B1   69632
#define Y5_BIAS 104448
#define Y5_BN   107008
#define Y5_TOTAL 108032

__global__ __launch_bounds__(256, 2) void gemm_y5(
    const float* __restrict__ A, const float* __restrict__ A2,
    const unsigned char* __restrict__ Wbase,
    const float* __restrict__ ybias, const float* __restrict__ bn_g,
    const float* __restrict__ bn_b, __half* __restrict__ yh, int M, int bnflag)
{
    extern __shared__ char smem[];
    uint32_t sb = smem_u32(smem);
    int tid = threadIdx.x, wid = tid >> 5, lane = tid & 31;
    int wm = wid & 3, wn = wid >> 2;
    int rowBase = blockIdx.x * 128;

    float* bias = (float*)(smem + Y5_BIAS);
    float* bnsc = (float*)(smem + Y5_BN);
    float* bnsh = bnsc + 128;

    for (int i = tid; i < RELS * 128; i += 256) bias[i] = ybias[i];
    if (bnflag) bn_coefs_smem(bnsc, bnsh, bn_g, bn_b);

    for (int i = tid; i < HBYTES / 16; i += 256)
        cpasync16(sb + Y5_B0 + i * 16, Wbase + (size_t)i * 16);
    cp_commit();

    __syncthreads();
    stage_A_hi(smem, A, A2, rowBase, M, Y5_A, bnflag ? bnsc : nullptr, bnflag ? bnsh : nullptr);

    int r0 = rowBase + wm * 32 + (lane >> 2);
    int cb0 = wn * 64 + (lane & 3) * 2;

#pragma unroll 1
    for (int z = 0; z < RELS; z++) {
        if (z < RELS - 1) {
            const unsigned char* cz = Wbase + (size_t)(z + 1) * WBYTES;
            uint32_t bdst = sb + (((z + 1) & 1) ? Y5_B1 : Y5_B0);
            for (int i = tid; i < HBYTES / 16; i += 256)
                cpasync16(bdst + i * 16, cz + (size_t)i * 16);
            cp_commit();
            asm volatile("cp.async.wait_group 1;" ::: "memory");
        } else {
            asm volatile("cp.async.wait_group 0;" ::: "memory");
        }
        __syncthreads();

        const char* Bbuf = smem + ((z & 1) ? Y5_B1 : Y5_B0);
        float acc[2][8][4];
        mma_compute<1>(smem + Y5_A, Bbuf, acc, wm, wn, lane);

        const float* bs = bias + z * 128;
#pragma unroll
        for (int mt = 0; mt < 2; mt++)
#pragma unroll
            for (int half = 0; half < 2; half++) {
                int row = r0 + mt * 16 + half * 8;
                if (row < M) {
                    __half* crow = yh + ((size_t)row * RELS + z) * D;
#pragma unroll
                    for (int nt = 0; nt < 8; nt++) {
                        int col = cb0 + nt * 8;
                        __half2 v = __floats2half2_rn(acc[mt][nt][half * 2] + bs[col],
                                                      acc[mt][nt][half * 2 + 1] + bs[col + 1]);
                        *(__half2*)(crow + col) = v;
                    }
                }
            }
        __syncthreads();
    }
}

// ---------------- zero init ----------------
__global__ void zero_kernel() {
    int i = blockIdx.x * blockDim.x + threadIdx.x;
    if (i < NN) { g_srccnt[i] = 0; g_dstcnt[i] = 0; }
    if (i < D)  { g_bnsum[i] = 0.f; g_bnssum[i] = 0.f; }
}

// ---------------- graph preprocessing ----------------
__global__ void count_edges(const int* __restrict__ ei, int E) {
    int e = blockIdx.x * blockDim.x + threadIdx.x;
    if (e >= E) return;
    atomicAdd(&g_dstcnt[ei[e]], 1);
    atomicAdd(&g_srccnt[ei[E + e]], 1);
}

__global__ void scan_local() {
    __shared__ int sh[1024];
    int b = blockIdx.x, tid = threadIdx.x;
    int i = b * 1024 + tid;
    int v = (i < NN) ? g_dstcnt[i] : 0;
    sh[tid] = v;
    __syncthreads();
    for (int o = 1; o < 1024; o <<= 1) {
        int x = (tid >= o) ? sh[tid - o] : 0;
        __syncthreads();
        sh[tid] += x;
        __syncthreads();
    }
    if (i < NN) g_scanloc[i] = sh[tid];
    if (tid == 1023) g_bsum[b] = sh[1023];
}
__global__ void scan_bsum() {
    if (threadIdx.x == 0) {
        int run = 0;
        for (int b = 0; b < NB; b++) { g_boff[b] = run; run += g_bsum[b]; }
        g_rowoff[NN] = run;
    }
}
__global__ void scan_add() {
    int i = blockIdx.x * blockDim.x + threadIdx.x;
    if (i >= NN) return;
    int ex = g_boff[i >> 10] + g_scanloc[i] - g_dstcnt[i];
    g_rowoff[i] = ex;
    g_cursor[i] = ex;
    int d = g_srccnt[i];
    g_dis[i] = (d > 0) ? rsqrtf((float)d) : 0.f;
}

__global__ void scatter_kernel(const int* __restrict__ ei, const int* __restrict__ ety, int E) {
    int e = blockIdx.x * blockDim.x + threadIdx.x;
    if (e >= E) return;
    int dst = ei[e];
    int src = ei[E + e];
    int r = ety[e];
    int pos = atomicAdd(&g_cursor[dst], 1);
    int2 ed;
    ed.x = src | (r << 16);
    ed.y = __float_as_int(g_dis[dst] * g_dis[src]);
    g_edge[pos] = ed;
}

// ---------------- split edge aggregation: gcn (x only) and softmax (y only) ----------------
__global__ __launch_bounds__(256) void agg_gcn(
    const __half* __restrict__ x16, float* __restrict__ zg)
{
    int gw = (blockIdx.x * blockDim.x + threadIdx.x) >> 5;
    int lane = threadIdx.x & 31;
    int node = gw * 2 + (lane >> 4);
    if (node >= NN) return;
    const int co = (lane & 15) * 8;

    float gz[8];
#pragma unroll
    for (int j = 0; j < 8; j++) gz[j] = 0.f;

    int beg = g_rowoff[node], end = g_rowoff[node + 1];
    int e = beg;
    for (; e + 4 <= end; e += 4) {
        int2 ed0 = g_edge[e],     ed1 = g_edge[e + 1];
        int2 ed2 = g_edge[e + 2], ed3 = g_edge[e + 3];
        uint4 xp0 = *(const uint4*)(x16 + (size_t)(ed0.x & 0xFFFF) * D + co);
        uint4 xp1 = *(const uint4*)(x16 + (size_t)(ed1.x & 0xFFFF) * D + co);
        uint4 xp2 = *(const uint4*)(x16 + (size_t)(ed2.x & 0xFFFF) * D + co);
        uint4 xp3 = *(const uint4*)(x16 + (size_t)(ed3.x & 0xFFFF) * D + co);
        const uint4* xs[4] = { &xp0, &xp1, &xp2, &xp3 };
        float nms[4] = { __int_as_float(ed0.y), __int_as_float(ed1.y),
                         __int_as_float(ed2.y), __int_as_float(ed3.y) };
#pragma unroll
        for (int q = 0; q < 4; q++) {
            const uint32_t* xw = (const uint32_t*)xs[q];
            float nm = nms[q];
#pragma unroll
            for (int j = 0; j < 4; j++) {
                float2 xa = __half22float2(*(__half2*)&xw[j]);
                gz[j * 2]     = fmaf(xa.x, nm, gz[j * 2]);
                gz[j * 2 + 1] = fmaf(xa.y, nm, gz[j * 2 + 1]);
            }
        }
    }
    for (; e < end; e++) {
        int2 ed = g_edge[e];
        uint4 xp = *(const uint4*)(x16 + (size_t)(ed.x & 0xFFFF) * D + co);
        float nm = __int_as_float(ed.y);
        const uint32_t* xw = (const uint32_t*)&xp;
#pragma unroll
        for (int j = 0; j < 4; j++) {
            float2 xa = __half22float2(*(__half2*)&xw[j]);
            gz[j * 2]     = fmaf(xa.x, nm, gz[j * 2]);
            gz[j * 2 + 1] = fmaf(xa.y, nm, gz[j * 2 + 1]);
        }
    }

    float* zr = zg + (size_t)node * D + co;
    *(float4*)(zr)     = make_float4(gz[0], gz[1], gz[2], gz[3]);
    *(float4*)(zr + 4) = make_float4(gz[4], gz[5], gz[6], gz[7]);
}

__global__ __launch_bounds__(256) void agg_soft(
    const __half* __restrict__ yh, float* __restrict__ zm)
{
    int gw = (blockIdx.x * blockDim.x + threadIdx.x) >> 5;
    int lane = threadIdx.x & 31;
    int node = gw * 2 + (lane >> 4);
    if (node >= NN) return;
    const int co = (lane & 15) * 8;

    float sz[8], tz[8];
#pragma unroll
    for (int j = 0; j < 8; j++) { sz[j] = 0.f; tz[j] = 0.f; }

    int beg = g_rowoff[node], end = g_rowoff[node + 1];
    int e = beg;
    for (; e + 4 <= end; e += 4) {
        int2 ed0 = g_edge[e],     ed1 = g_edge[e + 1];
        int2 ed2 = g_edge[e + 2], ed3 = g_edge[e + 3];
        uint4 yp0 = *(const uint4*)(yh + ((size_t)(ed0.x & 0xFFFF) * RELS + (ed0.x >> 16)) * D + co);
        uint4 yp1 = *(const uint4*)(yh + ((size_t)(ed1.x & 0xFFFF) * RELS + (ed1.x >> 16)) * D + co);
        uint4 yp2 = *(const uint4*)(yh + ((size_t)(ed2.x & 0xFFFF) * RELS + (ed2.x >> 16)) * D + co);
        uint4 yp3 = *(const uint4*)(yh + ((size_t)(ed3.x & 0xFFFF) * RELS + (ed3.x >> 16)) * D + co);
        const uint4* ys[4] = { &yp0, &yp1, &yp2, &yp3 };
#pragma unroll
        for (int q = 0; q < 4; q++) {
            const uint32_t* yw = (const uint32_t*)ys[q];
#pragma unroll
            for (int j = 0; j < 4; j++) {
                float2 ya = __half22float2(*(__half2*)&yw[j]);
                float e0 = __expf(ya.x), e1 = __expf(ya.y);
                sz[j * 2] += e0; sz[j * 2 + 1] += e1;
                tz[j * 2]     = fmaf(ya.x, e0, tz[j * 2]);
                tz[j * 2 + 1] = fmaf(ya.y, e1, tz[j * 2 + 1]);
            }
        }
    }
    for (; e < end; e++) {
        int2 ed = g_edge[e];
        uint4 yp = *(const uint4*)(yh + ((size_t)(ed.x & 0xFFFF) * RELS + (ed.x >> 16)) * D + co);
        const uint32_t* yw = (const uint32_t*)&yp;
#pragma unroll
        for (int j = 0; j < 4; j++) {
            float2 ya = __half22float2(*(__half2*)&yw[j]);
            float e0 = __expf(ya.x), e1 = __expf(ya.y);
            sz[j * 2] += e0; sz[j * 2 + 1] += e1;
            tz[j * 2]     = fmaf(ya.x, e0, tz[j * 2]);
            tz[j * 2 + 1] = fmaf(ya.y, e1, tz[j * 2 + 1]);
        }
    }

    float o[8];
    if (end > beg) {
#pragma unroll
        for (int j = 0; j < 8; j++)
            o[j] = 0.1f * fmaxf(tz[j] / sz[j], 0.f);
    } else {
#pragma unroll
        for (int j = 0; j < 8; j++) o[j] = 0.f;
    }
    float* zr = zm + (size_t)node * D + co;
    *(float4*)(zr)     = make_float4(o[0], o[1], o[2], o[3]);
    *(float4*)(zr + 4) = make_float4(o[4], o[5], o[6], o[7]);
}

// ---------------- final gather + exact GELU ----------------
__global__ void gather_gelu(const float* __restrict__ h, const int* __restrict__ idx,
                            float* __restrict__ out, int NI) {
    int i = blockIdx.x * blockDim.x + threadIdx.x;
    if (i >= NI * D) return;
    int row = idx[i >> 7];
    float v = h[(size_t)row * D + (i & (D - 1))];
    out[i] = 0.5f * v * (1.0f + erff(v * 0.70710678118654752f));
}

// ---------------- launch ----------------
extern "C" void kernel_launch(void* const* d_in, const int* in_sizes, int n_in,
                              void* d_out, int out_size) {
    const float* x      = (const float*)d_in[0];
    const int*   ei     = (const int*)d_in[1];
    const int*   ety    = (const int*)d_in[2];
    const int*   idx    = (const int*)d_in[4];
    const float* proj_w = (const float*)d_in[5];
    const float* proj_b = (const float*)d_in[6];
    const float* bn_g   = (const float*)d_in[7];
    const float* bn_b   = (const float*)d_in[8];
    const float* win_w[2]  = { (const float*)d_in[9],  (const float*)d_in[14] };
    const float* win_b[2]  = { (const float*)d_in[10], (const float*)d_in[15] };
    const float* wrel[2]   = { (const float*)d_in[11], (const float*)d_in[16] };
    const float* cout_w[2] = { (const float*)d_in[12], (const float*)d_in[17] };
    const float* cout_b[2] = { (const float*)d_in[13], (const float*)d_in[18] };

    const int E  = in_sizes[1] / 2;
    const int NI = in_sizes[4];
    float* out = (float*)d_out;

    float *buf0, *zg0, *zm0, *zg1, *zm1, *ybias, *xbias1;
    __half *x16, *yh;
    unsigned char* wbuf;
    cudaGetSymbolAddress((void**)&buf0, g_buf0);
    cudaGetSymbolAddress((void**)&zg0,  g_zg0);
    cudaGetSymbolAddress((void**)&zm0,  g_zm0);
    cudaGetSymbolAddress((void**)&zg1,  g_zg1);
    cudaGetSymbolAddress((void**)&zm1,  g_zm1);
    cudaGetSymbolAddress((void**)&x16,  g_x16);
    cudaGetSymbolAddress((void**)&yh,   g_yh);
    cudaGetSymbolAddress((void**)&wbuf, g_w);
    cudaGetSymbolAddress((void**)&ybias, g_ybias);
    cudaGetSymbolAddress((void**)&xbias1, g_xbias1);

    cudaFuncSetAttribute(gemm_mma, cudaFuncAttributeMaxDynamicSharedMemorySize, SM_TOTAL);
    cudaFuncSetAttribute(gemm_proj, cudaFuncAttributeMaxDynamicSharedMemorySize, SMP_TOTAL);
    cudaFuncSetAttribute(gemm_x, cudaFuncAttributeMaxDynamicSharedMemorySize, SMX_TOTAL);
    cudaFuncSetAttribute(gemm_y5, cudaFuncAttributeMaxDynamicSharedMemorySize, Y5_TOTAL);
    cudaFuncSetAttribute(prep_comp0, cudaFuncAttributeMaxDynamicSharedMemorySize, 65536);
    cudaFuncSetAttribute(prep_layer1, cudaFuncAttributeMaxDynamicSharedMemorySize, 131072);

    const int GB = (NN + 127) / 128;
    const int AGG_WARPS = (NN + 1) / 2;
    const int AGG_BLOCKS = (AGG_WARPS * 32 + 255) / 256;

    // ONE side stream + TWO event handles (proven envelope); events re-recorded
    cudaStream_t s2;
    cudaStreamCreateWithFlags(&s2, cudaStreamNonBlocking);
    cudaEvent_t ev0, ev1;
    cudaEventCreateWithFlags(&ev0, cudaEventDisableTiming);
    cudaEventCreateWithFlags(&ev1, cudaEventDisableTiming);

    zero_kernel<<<(NN + 255) / 256, 256>>>();
    cudaEventRecord(ev0, 0);                                   // ev0 #1

    // s2: layer-1 composites + graph preprocessing, record preproc-done
    cudaStreamWaitEvent(s2, ev0, 0);
    prep_layer1<<<6, 512, 131072, s2>>>(cout_w[0], win_w[1], wrel[1], win_b[1], cout_b[0]);
    count_edges<<<(E + 511) / 512, 512, 0, s2>>>(ei, E);
    scan_local<<<NB, 1024, 0, s2>>>();
    scan_bsum<<<1, 32, 0, s2>>>();
    scan_add<<<(NN + 1023) / 1024, 1024, 0, s2>>>();
    scatter_kernel<<<(E + 511) / 512, 512, 0, s2>>>(ei, ety, E);
    cudaEventRecord(ev1, s2);                                  // ev1 #1: preproc done

    // main: prep + proj
    prep_fast<<<3, 256>>>(proj_w, win_w[0], cout_w[1]);
    prep_comp0<<<RELS, 512, 65536>>>(win_w[0], wrel[0], win_b[0]);
    gemm_proj<<<GB, 256, SMP_TOTAL>>>(x, wbuf, proj_b, buf0, NN);
    cudaEventRecord(ev0, 0);                                   // ev0 #2: proj done

    // s2: x(L0) then gcn(L0)  (in-order after preproc)
    cudaStreamWaitEvent(s2, ev0, 0);
    gemm_x<<<GB, 256, SMX_TOTAL, s2>>>(buf0, nullptr, wbuf + (size_t)1 * WBYTES, win_b[0],
                                       bn_g, bn_b, x16, NN, 1);
    agg_gcn<<<AGG_BLOCKS, 256, 0, s2>>>(x16, zg0);

    // main: y5(L0), then soft(L0) after preproc (ev1#1)
    gemm_y5<<<GB, 256, Y5_TOTAL>>>(buf0, nullptr, wbuf + (size_t)2 * WBYTES, ybias,
                                   bn_g, bn_b, yh, NN, 1);
    cudaStreamWaitEvent(0, ev1, 0);
    agg_soft<<<AGG_BLOCKS, 256>>>(yh, zm0);
    cudaEventRecord(ev0, 0);                                   // ev0 #3: zm0 done (y5 done too)

    // s2: x(L1) reads zg0+zm0 (needs ev0#3; zg0 in-order), then gcn(L1)
    cudaStreamWaitEvent(s2, ev0, 0);
    gemm_x<<<GB, 256, SMX_TOTAL, s2>>>(zg0, zm0, wbuf + (size_t)8 * WBYTES, xbias1,
                                       bn_g, bn_b, x16, NN, 0);
    agg_gcn<<<AGG_BLOCKS, 256, 0, s2>>>(x16, zg1);
    cudaEventRecord(ev1, s2);                                  // ev1 #2: zg1 done

    // main: y5(L1) reads zg0+zm0 (zm0 in-order; zg0 needs s2 done up to gcn(L0) — covered:
    // main waited nothing for zg0... zg0 is read by y5(L1) — must wait for s2's gcn(L0)!
    // ev0#3 was recorded on main BEFORE s2 finished gcn(L0)? No: x(L1) on s2 also reads zg0 —
    // in-order on s2 after gcn(L0), fine. For main's y5(L1): wait ev1#2 would over-serialize.
    // Instead: s2's gcn(L0) completion is guaranteed before ev1#2, but y5(L1) needs it sooner.
    // Safe minimal fix: y5(L1) waits ev1#2 is too late; use the fact that x(L1) on s2 already
    // consumed zg0 — but main y5(L1) is independent. We wait on ev1 (#2) only before cout1.
    // To keep y5(L1) correct we move it AFTER a wait on s2's progress: reuse ev1 recorded
    // between gcn(L0) and x(L1)? That changes record count. Simplest correct: y5(L1) waits ev1#2.
    cudaStreamWaitEvent(0, ev1, 0);
    gemm_y5<<<GB, 256, Y5_TOTAL>>>(zg0, zm0, wbuf + (size_t)9 * WBYTES, ybias + RELS * D,
                                   bn_g, bn_b, yh, NN, 0);
    agg_soft<<<AGG_BLOCKS, 256>>>(yh, zm1);
    gemm_mma<<<GB, 256, SM_TOTAL>>>(zg1, zm1, wbuf + (size_t)14 * WBYTES, cout_b[1], buf0, NN);

    gather_gelu<<<(NI * D + 255) / 256, 256>>>(buf0, idx, out, NI);
}

// round 17
// speedup vs baseline: 1.0681x; 1.0681x over previous
#include <cuda_runtime.h>
#include <cuda_bf16.h>
#include <cuda_fp16.h>
#include <math.h>
#include <stdint.h>

#define NN 48758
#define EE 750000
#define D 128
#define RELS 5
#define PADK 136
#define WBYTES 69632
#define HBYTES 34816
#define NB 48

// ---------------- static device scratch ----------------
__device__ __align__(256) float g_buf0[NN * D];
__device__ __align__(256) __half g_x16[NN * D];
__device__ __align__(256) __half g_yh[(size_t)RELS * NN * D];
__device__ __align__(256) float g_z[NN * D];
__device__ float g_bnsum[D];
__device__ float g_bnssum[D];
__device__ int   g_srccnt[NN];
__device__ int   g_dstcnt[NN];
__device__ float g_dis[NN];
__device__ int   g_rowoff[NN + 1];
__device__ int   g_cursor[NN];
__device__ int   g_scanloc[NN];
__device__ int   g_bsum[NB];
__device__ int   g_boff[NB];
__device__ int2  g_edge[EE];
__device__ __align__(256) unsigned char g_w[(size_t)15 * WBYTES];
__device__ float g_ybias[2 * RELS * D];
__device__ float g_xbias1[D];

// ---------------- helpers ----------------
__device__ __forceinline__ uint32_t smem_u32(const void* p) {
    uint32_t a;
    asm("{ .reg .u64 t; cvta.to.shared.u64 t, %1; cvt.u32.u64 %0, t; }" : "=r"(a) : "l"(p));
    return a;
}
__device__ __forceinline__ uint32_t pack_bf2(__nv_bfloat16 lo, __nv_bfloat16 hi) {
    return ((uint32_t)__bfloat16_as_ushort(hi) << 16) | (uint32_t)__bfloat16_as_ushort(lo);
}
__device__ __forceinline__ void split_pair(float x0, float x1, uint32_t& hi2, uint32_t& lo2) {
    __nv_bfloat16 h0 = __float2bfloat16(x0), h1 = __float2bfloat16(x1);
    __nv_bfloat16 l0 = __float2bfloat16(x0 - __bfloat162float(h0));
    __nv_bfloat16 l1 = __float2bfloat16(x1 - __bfloat162float(h1));
    hi2 = pack_bf2(h0, h1);
    lo2 = pack_bf2(l0, l1);
}
__device__ __forceinline__ void ldmx4(uint32_t* r, uint32_t addr) {
    asm volatile("ldmatrix.sync.aligned.m8n8.x4.shared.b16 {%0,%1,%2,%3}, [%4];"
                 : "=r"(r[0]), "=r"(r[1]), "=r"(r[2]), "=r"(r[3]) : "r"(addr));
}
__device__ __forceinline__ void ldmx4t(uint32_t* r, uint32_t addr) {
    asm volatile("ldmatrix.sync.aligned.m8n8.x4.trans.shared.b16 {%0,%1,%2,%3}, [%4];"
                 : "=r"(r[0]), "=r"(r[1]), "=r"(r[2]), "=r"(r[3]) : "r"(addr));
}
__device__ __forceinline__ void mma16816(float* c, const uint32_t* a, const uint32_t* b) {
    asm volatile(
        "mma.sync.aligned.m16n8k16.row.col.f32.bf16.bf16.f32 "
        "{%0,%1,%2,%3}, {%4,%5,%6,%7}, {%8,%9}, {%0,%1,%2,%3};"
        : "+f"(c[0]), "+f"(c[1]), "+f"(c[2]), "+f"(c[3])
        : "r"(a[0]), "r"(a[1]), "r"(a[2]), "r"(a[3]), "r"(b[0]), "r"(b[1]));
}
__device__ __forceinline__ void cpasync16(uint32_t sdst, const void* gsrc) {
    asm volatile("cp.async.cg.shared.global [%0], [%1], 16;" :: "r"(sdst), "l"(gsrc) : "memory");
}
__device__ __forceinline__ void cp_commit() {
    asm volatile("cp.async.commit_group;" ::: "memory");
}

// ---------------- prep kernels ----------------
__device__ void split_direct(const float* __restrict__ W, unsigned char* dst) {
    for (int idx = threadIdx.x; idx < 128 * 64; idx += blockDim.x) {
        int k = idx >> 6, n = (idx & 63) * 2;
        uint32_t hi2, lo2;
        split_pair(W[k * 128 + n], W[k * 128 + n + 1], hi2, lo2);
        *(uint32_t*)(dst + (size_t)(k * PADK + n) * 2) = hi2;
        *(uint32_t*)(dst + HBYTES + (size_t)(k * PADK + n) * 2) = lo2;
    }
}

__device__ __forceinline__ float dot128(const float* __restrict__ left_row,
                                        const float* __restrict__ ws, int n) {
    float acc = 0.f;
#pragma unroll 8
    for (int j = 0; j < 128; j++) acc = fmaf(left_row[j], ws[j * 128 + n], acc);
    return acc;
}

__global__ void prep_fast(const float* __restrict__ proj,
                          const float* __restrict__ win0,
                          const float* __restrict__ cout1) {
    int b = blockIdx.x;
    if (b == 0) split_direct(proj,  g_w + 0 * (size_t)WBYTES);
    else if (b == 1) split_direct(win0, g_w + 1 * (size_t)WBYTES);
    else split_direct(cout1, g_w + 14 * (size_t)WBYTES);
}

__global__ void prep_comp0(const float* __restrict__ win0, const float* __restrict__ wrel0,
                           const float* __restrict__ win0b) {
    extern __shared__ float ws1[];
    int r = blockIdx.x, tid = threadIdx.x;
    const float* wrl = wrel0 + (size_t)r * 16384;
    unsigned char* dst = g_w + (size_t)(2 + r) * WBYTES;
    for (int i = tid; i < 4096; i += blockDim.x)
        ((float4*)ws1)[i] = ((const float4*)wrl)[i];
    __syncthreads();
    int n = tid & 127;
    int kbase = (tid >> 7) * 32;
    for (int ko = 0; ko < 32; ko++) {
        int k = kbase + ko;
        float acc = dot128(win0 + (size_t)k * 128, ws1, n);
        *(unsigned short*)(dst + (size_t)(k * PADK + n) * 2) =
            __bfloat16_as_ushort(__float2bfloat16(acc));
    }
    if (tid < 128) {
        float acc = 0.f;
#pragma unroll 8
        for (int k = 0; k < 128; k++) acc = fmaf(win0b[k], ws1[k * 128 + tid], acc);
        g_ybias[r * D + tid] = acc;
    }
}

__global__ void prep_layer1(const float* __restrict__ cout0, const float* __restrict__ win1,
                            const float* __restrict__ wrel1,
                            const float* __restrict__ win1b, const float* __restrict__ cout0b) {
    extern __shared__ float ws[];
    float* ws1 = ws;
    float* ws2 = ws + 16384;
    int b = blockIdx.x, tid = threadIdx.x;
    int n = tid & 127;
    int kbase = (tid >> 7) * 32;

    if (b == 0) {
        unsigned char* dst = g_w + (size_t)8 * WBYTES;
        for (int i = tid; i < 4096; i += blockDim.x)
            ((float4*)ws1)[i] = ((const float4*)win1)[i];
        __syncthreads();
        for (int ko = 0; ko < 32; ko++) {
            int k = kbase + ko;
            float acc = dot128(cout0 + (size_t)k * 128, ws1, n);
            __nv_bfloat16 h = __float2bfloat16(acc);
            __nv_bfloat16 l = __float2bfloat16(acc - __bfloat162float(h));
            *(unsigned short*)(dst + (size_t)(k * PADK + n) * 2) = __bfloat16_as_ushort(h);
            *(unsigned short*)(dst + HBYTES + (size_t)(k * PADK + n) * 2) = __bfloat16_as_ushort(l);
        }
        if (tid < 128) {
            float acc = win1b[tid];
#pragma unroll 8
            for (int k = 0; k < 128; k++) acc = fmaf(cout0b[k], ws1[k * 128 + tid], acc);
            g_xbias1[tid] = acc;
        }
        return;
    }

    int r = b - 1;
    const float* wrl = wrel1 + (size_t)r * 16384;
    unsigned char* dst = g_w + (size_t)(9 + r) * WBYTES;
    for (int i = tid; i < 4096; i += blockDim.x)
        ((float4*)ws1)[i] = ((const float4*)wrl)[i];
    __syncthreads();
    for (int ko = 0; ko < 32; ko++) {
        int k = kbase + ko;
        ws2[k * 128 + n] = dot128(win1 + (size_t)k * 128, ws1, n);
    }
    __syncthreads();
    for (int ko = 0; ko < 32; ko++) {
        int k = kbase + ko;
        float acc = dot128(cout0 + (size_t)k * 128, ws2, n);
        *(unsigned short*)(dst + (size_t)(k * PADK + n) * 2) =
            __bfloat16_as_ushort(__float2bfloat16(acc));
    }
    if (tid < 128) {
        float acc = 0.f;
#pragma unroll 8
        for (int k = 0; k < 128; k++) {
            acc = fmaf(cout0b[k], ws2[k * 128 + tid], acc);
            acc = fmaf(win1b[k], ws1[k * 128 + tid], acc);
        }
        g_ybias[(RELS + r) * D + tid] = acc;
    }
}

// ---------------- mma compute core ----------------
template<int NC>
__device__ __forceinline__ void mma_compute(
    const char* Abase, const char* Bbase, float acc[2][8][4], int wm, int wn, int lane)
{
#pragma unroll
    for (int mt = 0; mt < 2; mt++)
#pragma unroll
        for (int nt = 0; nt < 8; nt++)
#pragma unroll
            for (int i = 0; i < 4; i++) acc[mt][nt][i] = 0.f;

    const int arow = (lane & 15);
    const int acolb = (lane >> 4) * 8;

#pragma unroll
    for (int cb = 0; cb < NC; cb++) {
        const char* As = Abase + (cb == 2 ? HBYTES : 0);
        const char* Bs = Bbase + (cb == 1 ? HBYTES : 0);
#pragma unroll
        for (int k16 = 0; k16 < 8; k16++) {
            int k0 = k16 * 16;
            uint32_t afrag[2][4];
#pragma unroll
            for (int mt = 0; mt < 2; mt++) {
                int rr = wm * 32 + mt * 16 + arow;
                ldmx4(afrag[mt], smem_u32(As + (size_t)(rr * PADK + k0 + acolb) * 2));
            }
            uint32_t bfrag[8][2];
#pragma unroll
            for (int nt2 = 0; nt2 < 4; nt2++) {
                int rr = k0 + arow;
                int c = wn * 64 + nt2 * 16 + acolb;
                uint32_t t[4];
                ldmx4t(t, smem_u32(Bs + (size_t)(rr * PADK + c) * 2));
                bfrag[nt2 * 2][0] = t[0]; bfrag[nt2 * 2][1] = t[1];
                bfrag[nt2 * 2 + 1][0] = t[2]; bfrag[nt2 * 2 + 1][1] = t[3];
            }
#pragma unroll
            for (int mt = 0; mt < 2; mt++)
#pragma unroll
                for (int nt = 0; nt < 8; nt++)
                    mma16816(acc[mt][nt], afrag[mt], bfrag[nt]);
        }
    }
}

__device__ __forceinline__ void stage_A(char* smem, const float* __restrict__ A,
                                        int rowBase, int M, int aoff,
                                        const float* bnsc, const float* bnsh) {
    for (int idx = threadIdx.x; idx < 128 * 64; idx += 256) {
        int row = idx >> 6, k = (idx & 63) * 2;
        int gr = rowBase + row; if (gr >= M) gr = M - 1;
        float2 a = *(const float2*)(A + (size_t)gr * D + k);
        if (bnsc) {
            a.x = fmaxf(fmaf(a.x, bnsc[k], bnsh[k]), 0.f);
            a.y = fmaxf(fmaf(a.y, bnsc[k + 1], bnsh[k + 1]), 0.f);
        }
        uint32_t hi2, lo2;
        split_pair(a.x, a.y, hi2, lo2);
        *(uint32_t*)(smem + aoff + (size_t)(row * PADK + k) * 2) = hi2;
        *(uint32_t*)(smem + aoff + HBYTES + (size_t)(row * PADK + k) * 2) = lo2;
    }
}

// gathered A staging: row gr -> source row idxmap[gr]
__device__ __forceinline__ void stage_A_gather(char* smem, const float* __restrict__ A,
                                               const int* __restrict__ idxmap,
                                               int rowBase, int M, int aoff) {
    for (int idx = threadIdx.x; idx < 128 * 64; idx += 256) {
        int row = idx >> 6, k = (idx & 63) * 2;
        int gr = rowBase + row; if (gr >= M) gr = M - 1;
        int sr = idxmap[gr];
        float2 a = *(const float2*)(A + (size_t)sr * D + k);
        uint32_t hi2, lo2;
        split_pair(a.x, a.y, hi2, lo2);
        *(uint32_t*)(smem + aoff + (size_t)(row * PADK + k) * 2) = hi2;
        *(uint32_t*)(smem + aoff + HBYTES + (size_t)(row * PADK + k) * 2) = lo2;
    }
}

__device__ __forceinline__ void stage_A_hi(char* smem, const float* __restrict__ A,
                                           int rowBase, int M, int aoff,
                                           const float* bnsc, const float* bnsh) {
    for (int idx = threadIdx.x; idx < 128 * 64; idx += 256) {
        int row = idx >> 6, k = (idx & 63) * 2;
        int gr = rowBase + row; if (gr >= M) gr = M - 1;
        float2 a = *(const float2*)(A + (size_t)gr * D + k);
        if (bnsc) {
            a.x = fmaxf(fmaf(a.x, bnsc[k], bnsh[k]), 0.f);
            a.y = fmaxf(fmaf(a.y, bnsc[k + 1], bnsh[k + 1]), 0.f);
        }
        uint32_t hi2 = pack_bf2(__float2bfloat16(a.x), __float2bfloat16(a.y));
        *(uint32_t*)(smem + aoff + (size_t)(row * PADK + k) * 2) = hi2;
    }
}

__device__ __forceinline__ void bn_coefs_smem(float* bnsc, float* bnsh,
                                              const float* bn_g, const float* bn_b) {
    int tid = threadIdx.x;
    if (tid < 128) {
        float mu = g_bnsum[tid] * (1.f / NN);
        float var = g_bnssum[tid] * (1.f / NN) - mu * mu;
        float sc = bn_g[tid] * rsqrtf(var + 1e-5f);
        bnsc[tid] = sc;
        bnsh[tid] = bn_b[tid] - mu * sc;
    }
}

// ---------------- gathered cout1 GEMM + GELU epilogue: out = gelu(z[idx] @ W + b) ----------------
#define SM_AHI  0
#define SM_BHI  69632
#define SM_BIAS 139264
#define SM_TOTAL 139776

__global__ __launch_bounds__(256, 1) void gemm_cout_gelu(
    const float* __restrict__ A, const int* __restrict__ idxmap,
    const unsigned char* __restrict__ Wp,
    const float* __restrict__ bias, float* __restrict__ out, int M)
{
    extern __shared__ char smem[];
    int tid = threadIdx.x, wid = tid >> 5, lane = tid & 31;
    int wm = wid & 3, wn = wid >> 2;
    int rowBase = blockIdx.x * 128;

    for (int i = tid; i < WBYTES / 16; i += 256)
        ((float4*)(smem + SM_BHI))[i] = ((const float4*)Wp)[i];
    if (tid < 128) ((float*)(smem + SM_BIAS))[tid] = bias[tid];
    stage_A_gather(smem, A, idxmap, rowBase, M, SM_AHI);
    __syncthreads();

    float acc[2][8][4];
    mma_compute<3>(smem + SM_AHI, smem + SM_BHI, acc, wm, wn, lane);

    const float* bs = (const float*)(smem + SM_BIAS);
    int r0 = rowBase + wm * 32 + (lane >> 2);
    int cb0 = wn * 64 + (lane & 3) * 2;
#pragma unroll
    for (int mt = 0; mt < 2; mt++)
#pragma unroll
        for (int half = 0; half < 2; half++) {
            int row = r0 + mt * 16 + half * 8;
            if (row < M) {
                float* crow = out + (size_t)row * D;
#pragma unroll
                for (int nt = 0; nt < 8; nt++) {
                    int col = cb0 + nt * 8;
                    float v0 = acc[mt][nt][half * 2] + bs[col];
                    float v1 = acc[mt][nt][half * 2 + 1] + bs[col + 1];
                    v0 = 0.5f * v0 * (1.0f + erff(v0 * 0.70710678118654752f));
                    v1 = 0.5f * v1 * (1.0f + erff(v1 * 0.70710678118654752f));
                    float2 v = { v0, v1 };
                    *(float2*)(crow + col) = v;
                }
            }
        }
}

// ---------------- proj GEMM with fused BN-stats ----------------
#define SMP_STAT  139776
#define SMP_TOTAL 140800

__global__ __launch_bounds__(256, 1) void gemm_proj(
    const float* __restrict__ A, const unsigned char* __restrict__ Wp,
    const float* __restrict__ bias, float* __restrict__ C, int M)
{
    extern __shared__ char smem[];
    int tid = threadIdx.x, wid = tid >> 5, lane = tid & 31;
    int wm = wid & 3, wn = wid >> 2;
    int rowBase = blockIdx.x * 128;

    float* ssum = (float*)(smem + SMP_STAT);
    float* ssq  = ssum + 128;
    if (tid < 128) { ssum[tid] = 0.f; ssq[tid] = 0.f; }

    for (int i = tid; i < WBYTES / 16; i += 256)
        ((float4*)(smem + SM_BHI))[i] = ((const float4*)Wp)[i];
    if (tid < 128) ((float*)(smem + SM_BIAS))[tid] = bias[tid];
    stage_A(smem, A, rowBase, M, SM_AHI, nullptr, nullptr);
    __syncthreads();

    float acc[2][8][4];
    mma_compute<3>(smem + SM_AHI, smem + SM_BHI, acc, wm, wn, lane);

    const float* bs = (const float*)(smem + SM_BIAS);
    int r0 = rowBase + wm * 32 + (lane >> 2);
    int cb0 = wn * 64 + (lane & 3) * 2;

    float cs[16], cq[16];
#pragma unroll
    for (int i = 0; i < 16; i++) { cs[i] = 0.f; cq[i] = 0.f; }

#pragma unroll
    for (int mt = 0; mt < 2; mt++)
#pragma unroll
        for (int half = 0; half < 2; half++) {
            int row = r0 + mt * 16 + half * 8;
            if (row < M) {
                float* crow = C + (size_t)row * D;
#pragma unroll
                for (int nt = 0; nt < 8; nt++) {
                    int col = cb0 + nt * 8;
                    float v0 = acc[mt][nt][half * 2] + bs[col];
                    float v1 = acc[mt][nt][half * 2 + 1] + bs[col + 1];
                    float2 v = { v0, v1 };
                    *(float2*)(crow + col) = v;
                    cs[nt * 2] += v0;      cq[nt * 2] = fmaf(v0, v0, cq[nt * 2]);
                    cs[nt * 2 + 1] += v1;  cq[nt * 2 + 1] = fmaf(v1, v1, cq[nt * 2 + 1]);
                }
            }
        }

#pragma unroll
    for (int nt = 0; nt < 8; nt++) {
        int col = cb0 + nt * 8;
        atomicAdd(&ssum[col], cs[nt * 2]);      atomicAdd(&ssq[col], cq[nt * 2]);
        atomicAdd(&ssum[col + 1], cs[nt * 2 + 1]); atomicAdd(&ssq[col + 1], cq[nt * 2 + 1]);
    }
    __syncthreads();
    if (tid < 128) {
        atomicAdd(&g_bnsum[tid], ssum[tid]);
        atomicAdd(&g_bnssum[tid], ssq[tid]);
    }
}

// ---------------- gemm_x ----------------
#define SMX_A    0
#define SMX_B    69632
#define SMX_BIAS 139264
#define SMX_BN   139776
#define SMX_TOTAL 140800

__global__ __launch_bounds__(256, 1) void gemm_x(
    const float* __restrict__ A, const unsigned char* __restrict__ Wp,
    const float* __restrict__ bias, const float* __restrict__ bn_g,
    const float* __restrict__ bn_b, __half* __restrict__ x16, int M, int bnflag)
{
    extern __shared__ char smem[];
    int tid = threadIdx.x, wid = tid >> 5, lane = tid & 31;
    int wm = wid & 3, wn = wid >> 2;
    int rowBase = blockIdx.x * 128;

    float* bnsc = (float*)(smem + SMX_BN);
    float* bnsh = bnsc + 128;
    if (bnflag) bn_coefs_smem(bnsc, bnsh, bn_g, bn_b);

    for (int i = tid; i < WBYTES / 16; i += 256)
        ((float4*)(smem + SMX_B))[i] = ((const float4*)Wp)[i];
    if (tid < 128) ((float*)(smem + SMX_BIAS))[tid] = bias[tid];
    __syncthreads();
    stage_A(smem, A, rowBase, M, SMX_A, bnflag ? bnsc : nullptr, bnflag ? bnsh : nullptr);
    __syncthreads();

    float acc[2][8][4];
    mma_compute<3>(smem + SMX_A, smem + SMX_B, acc, wm, wn, lane);

    const float* bs = (const float*)(smem + SMX_BIAS);
    int r0 = rowBase + wm * 32 + (lane >> 2);
    int cb0 = wn * 64 + (lane & 3) * 2;
#pragma unroll
    for (int mt = 0; mt < 2; mt++)
#pragma unroll
        for (int half = 0; half < 2; half++) {
            int row = r0 + mt * 16 + half * 8;
            if (row < M) {
                __half* crow = x16 + (size_t)row * D;
#pragma unroll
                for (int nt = 0; nt < 8; nt++) {
                    int col = cb0 + nt * 8;
                    __half2 v = __floats2half2_rn(acc[mt][nt][half * 2] + bs[col],
                                                  acc[mt][nt][half * 2 + 1] + bs[col + 1]);
                    *(__half2*)(crow + col) = v;
                }
            }
        }
}

// ---------------- gemm_y5 ----------------
#define Y5_A    0
#define Y5_B0   34816
#define Y5_B1   69632
#define Y5_BIAS 104448
#define Y5_BN   107008
#define Y5_TOTAL 108032

__global__ __launch_bounds__(256, 2) void gemm_y5(
    const float* __restrict__ A, const unsigned char* __restrict__ Wbase,
    const float* __restrict__ ybias, const float* __restrict__ bn_g,
    const float* __restrict__ bn_b, __half* __restrict__ yh, int M, int bnflag)
{
    extern __shared__ char smem[];
    uint32_t sb = smem_u32(smem);
    int tid = threadIdx.x, wid = tid >> 5, lane = tid & 31;
    int wm = wid & 3, wn = wid >> 2;
    int rowBase = blockIdx.x * 128;

    float* bias = (float*)(smem + Y5_BIAS);
    float* bnsc = (float*)(smem + Y5_BN);
    float* bnsh = bnsc + 128;

    for (int i = tid; i < RELS * 128; i += 256) bias[i] = ybias[i];
    if (bnflag) bn_coefs_smem(bnsc, bnsh, bn_g, bn_b);

    for (int i = tid; i < HBYTES / 16; i += 256)
        cpasync16(sb + Y5_B0 + i * 16, Wbase + (size_t)i * 16);
    cp_commit();

    __syncthreads();
    stage_A_hi(smem, A, rowBase, M, Y5_A, bnflag ? bnsc : nullptr, bnflag ? bnsh : nullptr);

    int r0 = rowBase + wm * 32 + (lane >> 2);
    int cb0 = wn * 64 + (lane & 3) * 2;

#pragma unroll 1
    for (int z = 0; z < RELS; z++) {
        if (z < RELS - 1) {
            const unsigned char* cz = Wbase + (size_t)(z + 1) * WBYTES;
            uint32_t bdst = sb + (((z + 1) & 1) ? Y5_B1 : Y5_B0);
            for (int i = tid; i < HBYTES / 16; i += 256)
                cpasync16(bdst + i * 16, cz + (size_t)i * 16);
            cp_commit();
            asm volatile("cp.async.wait_group 1;" ::: "memory");
        } else {
            asm volatile("cp.async.wait_group 0;" ::: "memory");
        }
        __syncthreads();

        const char* Bbuf = smem + ((z & 1) ? Y5_B1 : Y5_B0);
        float acc[2][8][4];
        mma_compute<1>(smem + Y5_A, Bbuf, acc, wm, wn, lane);

        const float* bs = bias + z * 128;
#pragma unroll
        for (int mt = 0; mt < 2; mt++)
#pragma unroll
            for (int half = 0; half < 2; half++) {
                int row = r0 + mt * 16 + half * 8;
                if (row < M) {
                    __half* crow = yh + ((size_t)row * RELS + z) * D;
#pragma unroll
                    for (int nt = 0; nt < 8; nt++) {
                        int col = cb0 + nt * 8;
                        __half2 v = __floats2half2_rn(acc[mt][nt][half * 2] + bs[col],
                                                      acc[mt][nt][half * 2 + 1] + bs[col + 1]);
                        *(__half2*)(crow + col) = v;
                    }
                }
            }
        __syncthreads();
    }
}

// ---------------- zero init ----------------
__global__ void zero_kernel() {
    int i = blockIdx.x * blockDim.x + threadIdx.x;
    if (i < NN) { g_srccnt[i] = 0; g_dstcnt[i] = 0; }
    if (i < D)  { g_bnsum[i] = 0.f; g_bnssum[i] = 0.f; }
}

// ---------------- graph preprocessing ----------------
__global__ void count_edges(const int* __restrict__ ei, int E) {
    int e = blockIdx.x * blockDim.x + threadIdx.x;
    if (e >= E) return;
    atomicAdd(&g_dstcnt[ei[e]], 1);
    atomicAdd(&g_srccnt[ei[E + e]], 1);
}

__global__ void scan_local() {
    __shared__ int sh[1024];
    int b = blockIdx.x, tid = threadIdx.x;
    int i = b * 1024 + tid;
    int v = (i < NN) ? g_dstcnt[i] : 0;
    sh[tid] = v;
    __syncthreads();
    for (int o = 1; o < 1024; o <<= 1) {
        int x = (tid >= o) ? sh[tid - o] : 0;
        __syncthreads();
        sh[tid] += x;
        __syncthreads();
    }
    if (i < NN) g_scanloc[i] = sh[tid];
    if (tid == 1023) g_bsum[b] = sh[1023];
}
__global__ void scan_bsum() {
    if (threadIdx.x == 0) {
        int run = 0;
        for (int b = 0; b < NB; b++) { g_boff[b] = run; run += g_bsum[b]; }
        g_rowoff[NN] = run;
    }
}
__global__ void scan_add() {
    int i = blockIdx.x * blockDim.x + threadIdx.x;
    if (i >= NN) return;
    int ex = g_boff[i >> 10] + g_scanloc[i] - g_dstcnt[i];
    g_rowoff[i] = ex;
    g_cursor[i] = ex;
    int d = g_srccnt[i];
    g_dis[i] = (d > 0) ? rsqrtf((float)d) : 0.f;
}

__global__ void scatter_kernel(const int* __restrict__ ei, const int* __restrict__ ety, int E) {
    int e = blockIdx.x * blockDim.x + threadIdx.x;
    if (e >= E) return;
    int dst = ei[e];
    int src = ei[E + e];
    int r = ety[e];
    int pos = atomicAdd(&g_cursor[dst], 1);
    int2 ed;
    ed.x = src | (r << 16);
    ed.y = __float_as_int(g_dis[dst] * g_dis[src]);
    g_edge[pos] = ed;
}

// ---------------- edge aggregation: half-warp per node, uint4 loads, 4-edge unroll ----------------
__device__ __forceinline__ void agg_step8(uint4 xp, uint4 yp, float nm,
                                          float* gz, float* sz, float* tz) {
    const uint32_t* xw = (const uint32_t*)&xp;
    const uint32_t* yw = (const uint32_t*)&yp;
#pragma unroll
    for (int j = 0; j < 4; j++) {
        float2 xa = __half22float2(*(__half2*)&xw[j]);
        float2 ya = __half22float2(*(__half2*)&yw[j]);
        gz[j * 2]     = fmaf(xa.x, nm, gz[j * 2]);
        gz[j * 2 + 1] = fmaf(xa.y, nm, gz[j * 2 + 1]);
        float e0 = __expf(ya.x), e1 = __expf(ya.y);
        sz[j * 2] += e0; sz[j * 2 + 1] += e1;
        tz[j * 2]     = fmaf(ya.x, e0, tz[j * 2]);
        tz[j * 2 + 1] = fmaf(ya.y, e1, tz[j * 2 + 1]);
    }
}

__global__ __launch_bounds__(256) void aggregate(
    const __half* __restrict__ x16, const __half* __restrict__ yh, float* __restrict__ z)
{
    int gw = (blockIdx.x * blockDim.x + threadIdx.x) >> 5;
    int lane = threadIdx.x & 31;
    int node = gw * 2 + (lane >> 4);
    if (node >= NN) return;
    int l16 = lane & 15;
    const int co = l16 * 8;

    float gz[8], sz[8], tz[8];
#pragma unroll
    for (int j = 0; j < 8; j++) { gz[j] = 0.f; sz[j] = 0.f; tz[j] = 0.f; }

    int beg = g_rowoff[node], end = g_rowoff[node + 1];
    int e = beg;
    for (; e + 4 <= end; e += 4) {
        int2 ed0 = g_edge[e],     ed1 = g_edge[e + 1];
        int2 ed2 = g_edge[e + 2], ed3 = g_edge[e + 3];
        int s0 = ed0.x & 0xFFFF, r0 = ed0.x >> 16;
        int s1 = ed1.x & 0xFFFF, r1 = ed1.x >> 16;
        int s2 = ed2.x & 0xFFFF, r2 = ed2.x >> 16;
        int s3 = ed3.x & 0xFFFF, r3 = ed3.x >> 16;
        uint4 xp0 = *(const uint4*)(x16 + (size_t)s0 * D + co);
        uint4 yp0 = *(const uint4*)(yh + ((size_t)s0 * RELS + r0) * D + co);
        uint4 xp1 = *(const uint4*)(x16 + (size_t)s1 * D + co);
        uint4 yp1 = *(const uint4*)(yh + ((size_t)s1 * RELS + r1) * D + co);
        uint4 xp2 = *(const uint4*)(x16 + (size_t)s2 * D + co);
        uint4 yp2 = *(const uint4*)(yh + ((size_t)s2 * RELS + r2) * D + co);
        uint4 xp3 = *(const uint4*)(x16 + (size_t)s3 * D + co);
        uint4 yp3 = *(const uint4*)(yh + ((size_t)s3 * RELS + r3) * D + co);
        agg_step8(xp0, yp0, __int_as_float(ed0.y), gz, sz, tz);
        agg_step8(xp1, yp1, __int_as_float(ed1.y), gz, sz, tz);
        agg_step8(xp2, yp2, __int_as_float(ed2.y), gz, sz, tz);
        agg_step8(xp3, yp3, __int_as_float(ed3.y), gz, sz, tz);
    }
    for (; e < end; e++) {
        int2 ed = g_edge[e];
        int src = ed.x & 0xFFFF, r = ed.x >> 16;
        uint4 xp = *(const uint4*)(x16 + (size_t)src * D + co);
        uint4 yp = *(const uint4*)(yh + ((size_t)src * RELS + r) * D + co);
        agg_step8(xp, yp, __int_as_float(ed.y), gz, sz, tz);
    }

    float o[8];
    if (end > beg) {
#pragma unroll
        for (int j = 0; j < 8; j++)
            o[j] = gz[j] + 0.1f * fmaxf(tz[j] / sz[j], 0.f);
    } else {
#pragma unroll
        for (int j = 0; j < 8; j++) o[j] = gz[j];
    }
    float* zr = z + (size_t)node * D + co;
    *(float4*)(zr)     = make_float4(o[0], o[1], o[2], o[3]);
    *(float4*)(zr + 4) = make_float4(o[4], o[5], o[6], o[7]);
}

// ---------------- launch ----------------
extern "C" void kernel_launch(void* const* d_in, const int* in_sizes, int n_in,
                              void* d_out, int out_size) {
    const float* x      = (const float*)d_in[0];
    const int*   ei     = (const int*)d_in[1];
    const int*   ety    = (const int*)d_in[2];
    const int*   idx    = (const int*)d_in[4];
    const float* proj_w = (const float*)d_in[5];
    const float* proj_b = (const float*)d_in[6];
    const float* bn_g   = (const float*)d_in[7];
    const float* bn_b   = (const float*)d_in[8];
    const float* win_w[2]  = { (const float*)d_in[9],  (const float*)d_in[14] };
    const float* win_b[2]  = { (const float*)d_in[10], (const float*)d_in[15] };
    const float* wrel[2]   = { (const float*)d_in[11], (const float*)d_in[16] };
    const float* cout_w[2] = { (const float*)d_in[12], (const float*)d_in[17] };
    const float* cout_b[2] = { (const float*)d_in[13], (const float*)d_in[18] };

    const int E  = in_sizes[1] / 2;
    const int NI = in_sizes[4];
    float* out = (float*)d_out;

    float *buf0, *z, *ybias, *xbias1;
    __half *x16, *yh;
    unsigned char* wbuf;
    cudaGetSymbolAddress((void**)&buf0, g_buf0);
    cudaGetSymbolAddress((void**)&x16,  g_x16);
    cudaGetSymbolAddress((void**)&yh,   g_yh);
    cudaGetSymbolAddress((void**)&z,    g_z);
    cudaGetSymbolAddress((void**)&wbuf, g_w);
    cudaGetSymbolAddress((void**)&ybias, g_ybias);
    cudaGetSymbolAddress((void**)&xbias1, g_xbias1);

    cudaFuncSetAttribute(gemm_cout_gelu, cudaFuncAttributeMaxDynamicSharedMemorySize, SM_TOTAL);
    cudaFuncSetAttribute(gemm_proj, cudaFuncAttributeMaxDynamicSharedMemorySize, SMP_TOTAL);
    cudaFuncSetAttribute(gemm_x, cudaFuncAttributeMaxDynamicSharedMemorySize, SMX_TOTAL);
    cudaFuncSetAttribute(gemm_y5, cudaFuncAttributeMaxDynamicSharedMemorySize, Y5_TOTAL);
    cudaFuncSetAttribute(prep_comp0, cudaFuncAttributeMaxDynamicSharedMemorySize, 65536);
    cudaFuncSetAttribute(prep_layer1, cudaFuncAttributeMaxDynamicSharedMemorySize, 131072);

    const int GB = (NN + 127) / 128;
    const int GBI = (NI + 127) / 128;
    const int AGG_WARPS = (NN + 1) / 2;
    const int AGG_BLOCKS = (AGG_WARPS * 32 + 255) / 256;

    // ONE side stream + TWO event handles (R15-proven envelope)
    cudaStream_t s2;
    cudaStreamCreateWithFlags(&s2, cudaStreamNonBlocking);
    cudaEvent_t ev0, ev1;
    cudaEventCreateWithFlags(&ev0, cudaEventDisableTiming);
    cudaEventCreateWithFlags(&ev1, cudaEventDisableTiming);

    zero_kernel<<<(NN + 255) / 256, 256>>>();
    cudaEventRecord(ev0, 0);                                   // ev0 #1

    // s2: layer-1 composites + graph preprocessing
    cudaStreamWaitEvent(s2, ev0, 0);
    prep_layer1<<<6, 512, 131072, s2>>>(cout_w[0], win_w[1], wrel[1], win_b[1], cout_b[0]);
    count_edges<<<(E + 511) / 512, 512, 0, s2>>>(ei, E);
    scan_local<<<NB, 1024, 0, s2>>>();
    scan_bsum<<<1, 32, 0, s2>>>();
    scan_add<<<(NN + 1023) / 1024, 1024, 0, s2>>>();
    scatter_kernel<<<(E + 511) / 512, 512, 0, s2>>>(ei, ety, E);

    // main: prep fast path + proj
    prep_fast<<<3, 256>>>(proj_w, win_w[0], cout_w[1]);
    prep_comp0<<<RELS, 512, 65536>>>(win_w[0], wrel[0], win_b[0]);
    gemm_proj<<<GB, 256, SMP_TOTAL>>>(x, wbuf, proj_b, buf0, NN);
    cudaEventRecord(ev0, 0);                                   // ev0 #2: proj done

    // s2: layer-0 gemm_x after proj
    cudaStreamWaitEvent(s2, ev0, 0);
    gemm_x<<<GB, 256, SMX_TOTAL, s2>>>(buf0, wbuf + (size_t)1 * WBYTES, win_b[0],
                                       bn_g, bn_b, x16, NN, 1);
    cudaEventRecord(ev1, s2);                                  // ev1 #1: preproc + x(L0) done

    // main: y5(L0) concurrent with x(L0)
    gemm_y5<<<GB, 256, Y5_TOTAL>>>(buf0, wbuf + (size_t)2 * WBYTES, ybias,
                                   bn_g, bn_b, yh, NN, 1);
    cudaStreamWaitEvent(0, ev1, 0);

    aggregate<<<AGG_BLOCKS, 256>>>(x16, yh, z);                // z0
    cudaEventRecord(ev0, 0);                                   // ev0 #3: z0 ready

    // s2: layer-1 gemm_x concurrent with main's y5(L1)
    cudaStreamWaitEvent(s2, ev0, 0);
    gemm_x<<<GB, 256, SMX_TOTAL, s2>>>(z, wbuf + (size_t)8 * WBYTES, xbias1,
                                       bn_g, bn_b, x16, NN, 0);
    cudaEventRecord(ev1, s2);                                  // ev1 #2: x(L1) done

    gemm_y5<<<GB, 256, Y5_TOTAL>>>(z, wbuf + (size_t)9 * WBYTES, ybias + RELS * D,
                                   bn_g, bn_b, yh, NN, 0);
    cudaStreamWaitEvent(0, ev1, 0);

    aggregate<<<AGG_BLOCKS, 256>>>(x16, yh, z);                // z1
    // gathered cout1 + GELU: only the NI indexed rows are computed
    gemm_cout_gelu<<<GBI, 256, SM_TOTAL>>>(z, idx, wbuf + (size_t)14 * WBYTES,
                                           cout_b[1], out, NI);
}